// round 10
// baseline (speedup 1.0000x reference)
#include <cuda_runtime.h>

#define NEL 16777216   // B*C*D*H*W
typedef unsigned long long u64;

// Scratch. q/k/v in attention layout [b][s][head][d][e], ctx in x-layout [B][C][N].
__device__ __align__(16) float g_q[NEL];
__device__ __align__(16) float g_k[NEL];
__device__ __align__(16) float g_v[NEL];
__device__ __align__(16) float g_c[NEL];

__device__ __forceinline__ u64 pk2(float lo, float hi) {
    u64 r; asm("mov.b64 %0, {%1,%2};" : "=l"(r) : "f"(lo), "f"(hi)); return r;
}
__device__ __forceinline__ float2 upk2(u64 v) {
    float2 r; asm("mov.b64 {%0,%1}, %2;" : "=f"(r.x), "=f"(r.y) : "l"(v)); return r;
}
#define FMA2(d, a, b) asm("fma.rn.f32x2 %0, %1, %2, %0;" : "+l"(d) : "l"(a), "l"(b))

// ---------------------------------------------------------------------------
// W[64][64] ([o][k]) -> two conflict-free planes, 16B stride over ot.
// ---------------------------------------------------------------------------
__device__ __forceinline__ void stage_W2(float* A, float* B,
                                         const float* __restrict__ Wsrc) {
    for (int idx = threadIdx.x; idx < 2048; idx += 256) {
        int k = idx >> 5, t = idx & 31;
        int ot = t >> 2, j = t & 3;
        A[idx] = Wsrc[(ot*8 + j)*64 + k];
        B[idx] = Wsrc[(ot*8 + 4 + j)*64 + k];
    }
}

// Stage one 32-channel chunk of x[64][N] into xs[32][256].
__device__ __forceinline__ void stage_chunk(float* xs, const float* __restrict__ xsrc,
                                            int b, int n0, int kc) {
    const float4* xg = (const float4*)(xsrc + (u64)b*8388608 + n0);
    float4* xs4 = (float4*)xs;
    #pragma unroll
    for (int i = 0; i < 8; i++) {
        int idx = threadIdx.x + i*256;
        int c = idx >> 6, n4 = idx & 63;
        xs4[c*64 + n4] = xg[(u64)(kc*32 + c)*32768 + n4];
    }
}

// ---------------------------------------------------------------------------
// Generic projection -> attention layout [b][s][head][d][e].
// Block [64o x 256n], 256 threads, thread tile [8o x 8n], k-split 2x32.
// dst selected DEVICE-SIDE via `which` (device globals must not be passed
// from host code).
// ---------------------------------------------------------------------------
__global__ void __launch_bounds__(256, 2) k_proj(const float* __restrict__ x,
                                                 const float* __restrict__ W,
                                                 int which)
{
    __shared__ __align__(16) float xs[32*256];
    __shared__ __align__(16) float WA[2048];
    __shared__ __align__(16) float WB[2048];
    float* dst = (which == 0) ? g_q : (which == 1) ? g_k : g_v;
    int b = blockIdx.x >> 9;
    int n0 = (blockIdx.x & 511) << 8;
    stage_W2(WA, WB, W);

    int ot = threadIdx.x & 7, nt = threadIdx.x >> 3;   // n = nt*8
    u64 acc[8][4];
    #pragma unroll
    for (int o = 0; o < 8; o++)
        #pragma unroll
        for (int np = 0; np < 4; np++) acc[o][np] = 0ull;

    #pragma unroll 1
    for (int kc = 0; kc < 2; kc++) {
        __syncthreads();
        stage_chunk(xs, x, b, n0, kc);
        __syncthreads();
        #pragma unroll 4
        for (int k = 0; k < 32; k++) {
            int kg = kc*32 + k;
            float4 wa = *(const float4*)&WA[kg*32 + ot*4];
            float4 wb = *(const float4*)&WB[kg*32 + ot*4];
            u64 ws[8] = {pk2(wa.x,wa.x), pk2(wa.y,wa.y), pk2(wa.z,wa.z), pk2(wa.w,wa.w),
                         pk2(wb.x,wb.x), pk2(wb.y,wb.y), pk2(wb.z,wb.z), pk2(wb.w,wb.w)};
            const ulonglong2* xp = (const ulonglong2*)&xs[k*256 + nt*8];
            ulonglong2 x0 = xp[0], x1 = xp[1];
            u64 xv[4] = {x0.x, x0.y, x1.x, x1.y};
            #pragma unroll
            for (int o = 0; o < 8; o++)
                #pragma unroll
                for (int np = 0; np < 4; np++)
                    FMA2(acc[o][np], ws[o], xv[np]);
        }
    }

    int d = n0 >> 12;
    int sb = (n0 & 4095) + nt*8;
    float* gq = dst + (u64)b*8388608 + ot*256 + d*8;
    #pragma unroll
    for (int np = 0; np < 4; np++) {
        float2 f[8];
        #pragma unroll
        for (int o = 0; o < 8; o++) f[o] = upk2(acc[o][np]);
        float* p0 = gq + (u64)(sb + 2*np)*2048;
        ((float4*)p0)[0] = make_float4(f[0].x, f[1].x, f[2].x, f[3].x);
        ((float4*)p0)[1] = make_float4(f[4].x, f[5].x, f[6].x, f[7].x);
        float* p1 = gq + (u64)(sb + 2*np + 1)*2048;
        ((float4*)p1)[0] = make_float4(f[0].y, f[1].y, f[2].y, f[3].y);
        ((float4*)p1)[1] = make_float4(f[4].y, f[5].y, f[6].y, f[7].y);
    }
}

// ---------------------------------------------------------------------------
// Attention: one-pass softmax (no max-sub; |sim·scale| small), exp2 with
// folded scale, fused dot->exp->sum->V accumulate. Block=(b,head,8 s).
// ---------------------------------------------------------------------------
__global__ void __launch_bounds__(256) k_attn()
{
    __shared__ __align__(16) float ks[8][256];
    __shared__ __align__(16) float vsm[8][256];
    __shared__ __align__(16) float sctx[8*32*9];
    int warp = threadIdx.x >> 5, lane = threadIdx.x & 31;
    int blk = blockIdx.x;
    int s8   = blk & 511;
    int head = (blk >> 9) & 7;
    int b    = blk >> 12;
    int s = s8*8 + warp;
    int u = ((b << 12) + s)*8 + head;

    const float4* kp = (const float4*)(g_k + (u64)u*256);
    const float4* vp = (const float4*)(g_v + (u64)u*256);
    float4* ksw = (float4*)ks[warp];
    float4* vsw = (float4*)vsm[warp];
    ksw[lane*2]     = kp[lane*2];
    ksw[lane*2 + 1] = kp[lane*2 + 1];
    vsw[lane*2]     = vp[lane*2];
    vsw[lane*2 + 1] = vp[lane*2 + 1];

    const float4* qp = (const float4*)(g_q + (u64)u*256 + lane*8);
    float4 q0 = qp[0], q1 = qp[1];
    u64 qv0 = pk2(q0.x, q0.y), qv1 = pk2(q0.z, q0.w);
    u64 qv2 = pk2(q1.x, q1.y), qv3 = pk2(q1.z, q1.w);
    __syncwarp();

    const float CEXP = 0.35355339059327373f * 1.4426950408889634f;
    float ssA = 0.f, ssB = 0.f;
    u64 c0 = 0ull, c1 = 0ull, c2 = 0ull, c3 = 0ull;
    #pragma unroll
    for (int j = 0; j < 32; j++) {
        const ulonglong2* kq = (const ulonglong2*)&ks[warp][j*8];
        ulonglong2 ka = kq[0], kb = kq[1];
        u64 a0 = 0ull, a1 = 0ull;
        FMA2(a0, ka.x, qv0); FMA2(a1, ka.y, qv1);
        FMA2(a0, kb.x, qv2); FMA2(a1, kb.y, qv3);
        float2 f0 = upk2(a0), f1 = upk2(a1);
        float p = exp2f(((f0.x + f0.y) + (f1.x + f1.y)) * CEXP);
        if (j & 1) ssB += p; else ssA += p;
        u64 pp = pk2(p, p);
        const ulonglong2* vq = (const ulonglong2*)&vsm[warp][j*8];
        ulonglong2 va = vq[0], vb = vq[1];
        FMA2(c0, va.x, pp); FMA2(c1, va.y, pp);
        FMA2(c2, vb.x, pp); FMA2(c3, vb.y, pp);
    }

    float inv = 1.f / (ssA + ssB);
    float2 r0 = upk2(c0), r1 = upk2(c1), r2 = upk2(c2), r3 = upk2(c3);
    float vals[8] = {r0.x*inv, r0.y*inv, r1.x*inv, r1.y*inv,
                     r2.x*inv, r2.y*inv, r3.x*inv, r3.y*inv};
    #pragma unroll
    for (int e = 0; e < 8; e++)
        sctx[e*288 + lane*9 + warp] = vals[e];
    __syncthreads();

    int e = threadIdx.x >> 5, d = threadIdx.x & 31;
    const float* sp = &sctx[e*288 + d*9];
    float4 f0 = make_float4(sp[0], sp[1], sp[2], sp[3]);
    float4 f1 = make_float4(sp[4], sp[5], sp[6], sp[7]);
    float* dst = g_c + (u64)b*8388608 + (head*8 + e)*131072 + d*4096 + s8*8;
    ((float4*)dst)[0] = f0;
    ((float4*)dst)[1] = f1;
}

// ---------------------------------------------------------------------------
// O projection: same GEMM core, reads g_c (x-layout) device-side,
// contiguous stores to out.
// ---------------------------------------------------------------------------
__global__ void __launch_bounds__(256, 2) k_proj_o(const float* __restrict__ W,
                                                   float* __restrict__ out)
{
    __shared__ __align__(16) float xs[32*256];
    __shared__ __align__(16) float WA[2048];
    __shared__ __align__(16) float WB[2048];
    int b = blockIdx.x >> 9;
    int n0 = (blockIdx.x & 511) << 8;
    stage_W2(WA, WB, W);

    int ot = threadIdx.x & 7, nt = threadIdx.x >> 3;
    u64 acc[8][4];
    #pragma unroll
    for (int o = 0; o < 8; o++)
        #pragma unroll
        for (int np = 0; np < 4; np++) acc[o][np] = 0ull;

    #pragma unroll 1
    for (int kc = 0; kc < 2; kc++) {
        __syncthreads();
        stage_chunk(xs, g_c, b, n0, kc);
        __syncthreads();
        #pragma unroll 4
        for (int k = 0; k < 32; k++) {
            int kg = kc*32 + k;
            float4 wa = *(const float4*)&WA[kg*32 + ot*4];
            float4 wb = *(const float4*)&WB[kg*32 + ot*4];
            u64 ws[8] = {pk2(wa.x,wa.x), pk2(wa.y,wa.y), pk2(wa.z,wa.z), pk2(wa.w,wa.w),
                         pk2(wb.x,wb.x), pk2(wb.y,wb.y), pk2(wb.z,wb.z), pk2(wb.w,wb.w)};
            const ulonglong2* xp = (const ulonglong2*)&xs[k*256 + nt*8];
            ulonglong2 x0 = xp[0], x1 = xp[1];
            u64 xv[4] = {x0.x, x0.y, x1.x, x1.y};
            #pragma unroll
            for (int o = 0; o < 8; o++)
                #pragma unroll
                for (int np = 0; np < 4; np++)
                    FMA2(acc[o][np], ws[o], xv[np]);
        }
    }

    float* ob = out + (u64)b*8388608 + n0 + nt*8;
    #pragma unroll
    for (int o = 0; o < 8; o++) {
        float* oc = ob + (u64)(ot*8 + o)*131072;
        float2 a0 = upk2(acc[o][0]), a1 = upk2(acc[o][1]);
        float2 a2 = upk2(acc[o][2]), a3 = upk2(acc[o][3]);
        ((float4*)oc)[0] = make_float4(a0.x, a0.y, a1.x, a1.y);
        ((float4*)oc)[1] = make_float4(a2.x, a2.y, a3.x, a3.y);
    }
}

extern "C" void kernel_launch(void* const* d_in, const int* in_sizes, int n_in,
                              void* d_out, int out_size)
{
    const float* qf = (const float*)d_in[0];
    const float* kf = (const float*)d_in[1];
    const float* Wq = (const float*)d_in[2];
    const float* Wk = (const float*)d_in[3];
    const float* Wv = (const float*)d_in[4];
    const float* Wo = (const float*)d_in[5];
    float* out = (float*)d_out;

    k_proj  <<<1024, 256>>>(qf, Wq, 0);
    k_proj  <<<1024, 256>>>(kf, Wk, 1);
    k_proj  <<<1024, 256>>>(kf, Wv, 2);
    k_attn  <<<8192, 256>>>();
    k_proj_o<<<1024, 256>>>(Wo, out);
}

// round 11
// speedup vs baseline: 1.0009x; 1.0009x over previous
#include <cuda_runtime.h>

#define NEL 16777216   // B*C*D*H*W
typedef unsigned long long u64;

// Scratch. q/k/v in attention layout [b][s][head][d][e], ctx in x-layout [B][C][N].
__device__ __align__(16) float g_q[NEL];
__device__ __align__(16) float g_k[NEL];
__device__ __align__(16) float g_v[NEL];
__device__ __align__(16) float g_c[NEL];

__device__ __forceinline__ u64 pk2(float lo, float hi) {
    u64 r; asm("mov.b64 %0, {%1,%2};" : "=l"(r) : "f"(lo), "f"(hi)); return r;
}
__device__ __forceinline__ float2 upk2(u64 v) {
    float2 r; asm("mov.b64 {%0,%1}, %2;" : "=f"(r.x), "=f"(r.y) : "l"(v)); return r;
}
#define FMA2(d, a, b) asm("fma.rn.f32x2 %0, %1, %2, %0;" : "+l"(d) : "l"(a), "l"(b))

// ---------------------------------------------------------------------------
// W[64][64] ([o][k]) -> two conflict-free planes, 16B stride over ot.
// ---------------------------------------------------------------------------
__device__ __forceinline__ void stage_W2(float* A, float* B,
                                         const float* __restrict__ Wsrc) {
    for (int idx = threadIdx.x; idx < 2048; idx += 256) {
        int k = idx >> 5, t = idx & 31;
        int ot = t >> 2, j = t & 3;
        A[idx] = Wsrc[(ot*8 + j)*64 + k];
        B[idx] = Wsrc[(ot*8 + 4 + j)*64 + k];
    }
}

// Stage one 32-channel chunk of x[64][N] into xs[32][256].
__device__ __forceinline__ void stage_chunk(float* xs, const float* __restrict__ xsrc,
                                            int b, int n0, int kc) {
    const float4* xg = (const float4*)(xsrc + (u64)b*8388608 + n0);
    float4* xs4 = (float4*)xs;
    #pragma unroll
    for (int i = 0; i < 8; i++) {
        int idx = threadIdx.x + i*256;
        int c = idx >> 6, n4 = idx & 63;
        xs4[c*64 + n4] = xg[(u64)(kc*32 + c)*32768 + n4];
    }
}

// ---------------------------------------------------------------------------
// Generic projection -> attention layout [b][s][head][d][e].
// Block [64o x 256n], 256 threads, thread tile [8o x 8n], k-split 2x32.
// dst selected DEVICE-SIDE via `which` (device globals must not be passed
// from host code).
// ---------------------------------------------------------------------------
__global__ void __launch_bounds__(256, 2) k_proj(const float* __restrict__ x,
                                                 const float* __restrict__ W,
                                                 int which)
{
    __shared__ __align__(16) float xs[32*256];
    __shared__ __align__(16) float WA[2048];
    __shared__ __align__(16) float WB[2048];
    float* dst = (which == 0) ? g_q : (which == 1) ? g_k : g_v;
    int b = blockIdx.x >> 9;
    int n0 = (blockIdx.x & 511) << 8;
    stage_W2(WA, WB, W);

    int ot = threadIdx.x & 7, nt = threadIdx.x >> 3;   // n = nt*8
    u64 acc[8][4];
    #pragma unroll
    for (int o = 0; o < 8; o++)
        #pragma unroll
        for (int np = 0; np < 4; np++) acc[o][np] = 0ull;

    #pragma unroll 1
    for (int kc = 0; kc < 2; kc++) {
        __syncthreads();
        stage_chunk(xs, x, b, n0, kc);
        __syncthreads();
        #pragma unroll 4
        for (int k = 0; k < 32; k++) {
            int kg = kc*32 + k;
            float4 wa = *(const float4*)&WA[kg*32 + ot*4];
            float4 wb = *(const float4*)&WB[kg*32 + ot*4];
            u64 ws[8] = {pk2(wa.x,wa.x), pk2(wa.y,wa.y), pk2(wa.z,wa.z), pk2(wa.w,wa.w),
                         pk2(wb.x,wb.x), pk2(wb.y,wb.y), pk2(wb.z,wb.z), pk2(wb.w,wb.w)};
            const ulonglong2* xp = (const ulonglong2*)&xs[k*256 + nt*8];
            ulonglong2 x0 = xp[0], x1 = xp[1];
            u64 xv[4] = {x0.x, x0.y, x1.x, x1.y};
            #pragma unroll
            for (int o = 0; o < 8; o++)
                #pragma unroll
                for (int np = 0; np < 4; np++)
                    FMA2(acc[o][np], ws[o], xv[np]);
        }
    }

    int d = n0 >> 12;
    int sb = (n0 & 4095) + nt*8;
    float* gq = dst + (u64)b*8388608 + ot*256 + d*8;
    #pragma unroll
    for (int np = 0; np < 4; np++) {
        float2 f[8];
        #pragma unroll
        for (int o = 0; o < 8; o++) f[o] = upk2(acc[o][np]);
        float* p0 = gq + (u64)(sb + 2*np)*2048;
        ((float4*)p0)[0] = make_float4(f[0].x, f[1].x, f[2].x, f[3].x);
        ((float4*)p0)[1] = make_float4(f[4].x, f[5].x, f[6].x, f[7].x);
        float* p1 = gq + (u64)(sb + 2*np + 1)*2048;
        ((float4*)p1)[0] = make_float4(f[0].y, f[1].y, f[2].y, f[3].y);
        ((float4*)p1)[1] = make_float4(f[4].y, f[5].y, f[6].y, f[7].y);
    }
}

// ---------------------------------------------------------------------------
// Attention: one-pass softmax (no max-sub; |sim·scale| small), exp2 with
// folded scale, fused dot->exp->sum->V accumulate. Block=(b,head,8 s).
// ---------------------------------------------------------------------------
__global__ void __launch_bounds__(256) k_attn()
{
    __shared__ __align__(16) float ks[8][256];
    __shared__ __align__(16) float vsm[8][256];
    __shared__ __align__(16) float sctx[8*32*9];
    int warp = threadIdx.x >> 5, lane = threadIdx.x & 31;
    int blk = blockIdx.x;
    int s8   = blk & 511;
    int head = (blk >> 9) & 7;
    int b    = blk >> 12;
    int s = s8*8 + warp;
    int u = ((b << 12) + s)*8 + head;

    const float4* kp = (const float4*)(g_k + (u64)u*256);
    const float4* vp = (const float4*)(g_v + (u64)u*256);
    float4* ksw = (float4*)ks[warp];
    float4* vsw = (float4*)vsm[warp];
    ksw[lane*2]     = kp[lane*2];
    ksw[lane*2 + 1] = kp[lane*2 + 1];
    vsw[lane*2]     = vp[lane*2];
    vsw[lane*2 + 1] = vp[lane*2 + 1];

    const float4* qp = (const float4*)(g_q + (u64)u*256 + lane*8);
    float4 q0 = qp[0], q1 = qp[1];
    u64 qv0 = pk2(q0.x, q0.y), qv1 = pk2(q0.z, q0.w);
    u64 qv2 = pk2(q1.x, q1.y), qv3 = pk2(q1.z, q1.w);
    __syncwarp();

    const float CEXP = 0.35355339059327373f * 1.4426950408889634f;
    float ssA = 0.f, ssB = 0.f;
    u64 c0 = 0ull, c1 = 0ull, c2 = 0ull, c3 = 0ull;
    #pragma unroll
    for (int j = 0; j < 32; j++) {
        const ulonglong2* kq = (const ulonglong2*)&ks[warp][j*8];
        ulonglong2 ka = kq[0], kb = kq[1];
        u64 a0 = 0ull, a1 = 0ull;
        FMA2(a0, ka.x, qv0); FMA2(a1, ka.y, qv1);
        FMA2(a0, kb.x, qv2); FMA2(a1, kb.y, qv3);
        float2 f0 = upk2(a0), f1 = upk2(a1);
        float p = exp2f(((f0.x + f0.y) + (f1.x + f1.y)) * CEXP);
        if (j & 1) ssB += p; else ssA += p;
        u64 pp = pk2(p, p);
        const ulonglong2* vq = (const ulonglong2*)&vsm[warp][j*8];
        ulonglong2 va = vq[0], vb = vq[1];
        FMA2(c0, va.x, pp); FMA2(c1, va.y, pp);
        FMA2(c2, vb.x, pp); FMA2(c3, vb.y, pp);
    }

    float inv = 1.f / (ssA + ssB);
    float2 r0 = upk2(c0), r1 = upk2(c1), r2 = upk2(c2), r3 = upk2(c3);
    float vals[8] = {r0.x*inv, r0.y*inv, r1.x*inv, r1.y*inv,
                     r2.x*inv, r2.y*inv, r3.x*inv, r3.y*inv};
    #pragma unroll
    for (int e = 0; e < 8; e++)
        sctx[e*288 + lane*9 + warp] = vals[e];
    __syncthreads();

    int e = threadIdx.x >> 5, d = threadIdx.x & 31;
    const float* sp = &sctx[e*288 + d*9];
    float4 f0 = make_float4(sp[0], sp[1], sp[2], sp[3]);
    float4 f1 = make_float4(sp[4], sp[5], sp[6], sp[7]);
    float* dst = g_c + (u64)b*8388608 + (head*8 + e)*131072 + d*4096 + s8*8;
    ((float4*)dst)[0] = f0;
    ((float4*)dst)[1] = f1;
}

// ---------------------------------------------------------------------------
// O projection: same GEMM core, reads g_c (x-layout) device-side,
// contiguous stores to out.
// ---------------------------------------------------------------------------
__global__ void __launch_bounds__(256, 2) k_proj_o(const float* __restrict__ W,
                                                   float* __restrict__ out)
{
    __shared__ __align__(16) float xs[32*256];
    __shared__ __align__(16) float WA[2048];
    __shared__ __align__(16) float WB[2048];
    int b = blockIdx.x >> 9;
    int n0 = (blockIdx.x & 511) << 8;
    stage_W2(WA, WB, W);

    int ot = threadIdx.x & 7, nt = threadIdx.x >> 3;
    u64 acc[8][4];
    #pragma unroll
    for (int o = 0; o < 8; o++)
        #pragma unroll
        for (int np = 0; np < 4; np++) acc[o][np] = 0ull;

    #pragma unroll 1
    for (int kc = 0; kc < 2; kc++) {
        __syncthreads();
        stage_chunk(xs, g_c, b, n0, kc);
        __syncthreads();
        #pragma unroll 4
        for (int k = 0; k < 32; k++) {
            int kg = kc*32 + k;
            float4 wa = *(const float4*)&WA[kg*32 + ot*4];
            float4 wb = *(const float4*)&WB[kg*32 + ot*4];
            u64 ws[8] = {pk2(wa.x,wa.x), pk2(wa.y,wa.y), pk2(wa.z,wa.z), pk2(wa.w,wa.w),
                         pk2(wb.x,wb.x), pk2(wb.y,wb.y), pk2(wb.z,wb.z), pk2(wb.w,wb.w)};
            const ulonglong2* xp = (const ulonglong2*)&xs[k*256 + nt*8];
            ulonglong2 x0 = xp[0], x1 = xp[1];
            u64 xv[4] = {x0.x, x0.y, x1.x, x1.y};
            #pragma unroll
            for (int o = 0; o < 8; o++)
                #pragma unroll
                for (int np = 0; np < 4; np++)
                    FMA2(acc[o][np], ws[o], xv[np]);
        }
    }

    float* ob = out + (u64)b*8388608 + n0 + nt*8;
    #pragma unroll
    for (int o = 0; o < 8; o++) {
        float* oc = ob + (u64)(ot*8 + o)*131072;
        float2 a0 = upk2(acc[o][0]), a1 = upk2(acc[o][1]);
        float2 a2 = upk2(acc[o][2]), a3 = upk2(acc[o][3]);
        ((float4*)oc)[0] = make_float4(a0.x, a0.y, a1.x, a1.y);
        ((float4*)oc)[1] = make_float4(a2.x, a2.y, a3.x, a3.y);
    }
}

extern "C" void kernel_launch(void* const* d_in, const int* in_sizes, int n_in,
                              void* d_out, int out_size)
{
    const float* qf = (const float*)d_in[0];
    const float* kf = (const float*)d_in[1];
    const float* Wq = (const float*)d_in[2];
    const float* Wk = (const float*)d_in[3];
    const float* Wv = (const float*)d_in[4];
    const float* Wo = (const float*)d_in[5];
    float* out = (float*)d_out;

    k_proj  <<<1024, 256>>>(qf, Wq, 0);
    k_proj  <<<1024, 256>>>(kf, Wk, 1);
    k_proj  <<<1024, 256>>>(kf, Wv, 2);
    k_attn  <<<8192, 256>>>();
    k_proj_o<<<1024, 256>>>(Wo, out);
}

// round 12
// speedup vs baseline: 1.0016x; 1.0006x over previous
#include <cuda_runtime.h>

#define NEL 16777216   // B*C*D*H*W
typedef unsigned long long u64;

// Scratch. q/k/v in attention layout [b][s][head][d][e], ctx in x-layout [B][C][N].
__device__ __align__(16) float g_q[NEL];
__device__ __align__(16) float g_k[NEL];
__device__ __align__(16) float g_v[NEL];
__device__ __align__(16) float g_c[NEL];

__device__ __forceinline__ u64 pk2(float lo, float hi) {
    u64 r; asm("mov.b64 %0, {%1,%2};" : "=l"(r) : "f"(lo), "f"(hi)); return r;
}
__device__ __forceinline__ float2 upk2(u64 v) {
    float2 r; asm("mov.b64 {%0,%1}, %2;" : "=f"(r.x), "=f"(r.y) : "l"(v)); return r;
}
#define FMA2(d, a, b) asm("fma.rn.f32x2 %0, %1, %2, %0;" : "+l"(d) : "l"(a), "l"(b))

// ---------------------------------------------------------------------------
// W[64][64] ([o][k]) -> two conflict-free planes, 16B stride over ot.
// ---------------------------------------------------------------------------
__device__ __forceinline__ void stage_W2(float* A, float* B,
                                         const float* __restrict__ Wsrc) {
    for (int idx = threadIdx.x; idx < 2048; idx += 256) {
        int k = idx >> 5, t = idx & 31;
        int ot = t >> 2, j = t & 3;
        A[idx] = Wsrc[(ot*8 + j)*64 + k];
        B[idx] = Wsrc[(ot*8 + 4 + j)*64 + k];
    }
}

// Stage one 32-channel chunk of x[64][N] into xs[32][256].
__device__ __forceinline__ void stage_chunk(float* xs, const float* __restrict__ xsrc,
                                            int b, int n0, int kc) {
    const float4* xg = (const float4*)(xsrc + (u64)b*8388608 + n0);
    float4* xs4 = (float4*)xs;
    #pragma unroll
    for (int i = 0; i < 8; i++) {
        int idx = threadIdx.x + i*256;
        int c = idx >> 6, n4 = idx & 63;
        xs4[c*64 + n4] = xg[(u64)(kc*32 + c)*32768 + n4];
    }
}

// ---------------------------------------------------------------------------
// Generic projection -> attention layout [b][s][head][d][e].
// Block [64o x 256n], 256 threads, thread tile [8o x 8n], k-split 2x32.
// dst selected DEVICE-SIDE via `which` (device globals must not be passed
// from host code).
// ---------------------------------------------------------------------------
__global__ void __launch_bounds__(256, 2) k_proj(const float* __restrict__ x,
                                                 const float* __restrict__ W,
                                                 int which)
{
    __shared__ __align__(16) float xs[32*256];
    __shared__ __align__(16) float WA[2048];
    __shared__ __align__(16) float WB[2048];
    float* dst = (which == 0) ? g_q : (which == 1) ? g_k : g_v;
    int b = blockIdx.x >> 9;
    int n0 = (blockIdx.x & 511) << 8;
    stage_W2(WA, WB, W);

    int ot = threadIdx.x & 7, nt = threadIdx.x >> 3;   // n = nt*8
    u64 acc[8][4];
    #pragma unroll
    for (int o = 0; o < 8; o++)
        #pragma unroll
        for (int np = 0; np < 4; np++) acc[o][np] = 0ull;

    #pragma unroll 1
    for (int kc = 0; kc < 2; kc++) {
        __syncthreads();
        stage_chunk(xs, x, b, n0, kc);
        __syncthreads();
        #pragma unroll 4
        for (int k = 0; k < 32; k++) {
            int kg = kc*32 + k;
            float4 wa = *(const float4*)&WA[kg*32 + ot*4];
            float4 wb = *(const float4*)&WB[kg*32 + ot*4];
            u64 ws[8] = {pk2(wa.x,wa.x), pk2(wa.y,wa.y), pk2(wa.z,wa.z), pk2(wa.w,wa.w),
                         pk2(wb.x,wb.x), pk2(wb.y,wb.y), pk2(wb.z,wb.z), pk2(wb.w,wb.w)};
            const ulonglong2* xp = (const ulonglong2*)&xs[k*256 + nt*8];
            ulonglong2 x0 = xp[0], x1 = xp[1];
            u64 xv[4] = {x0.x, x0.y, x1.x, x1.y};
            #pragma unroll
            for (int o = 0; o < 8; o++)
                #pragma unroll
                for (int np = 0; np < 4; np++)
                    FMA2(acc[o][np], ws[o], xv[np]);
        }
    }

    int d = n0 >> 12;
    int sb = (n0 & 4095) + nt*8;
    float* gq = dst + (u64)b*8388608 + ot*256 + d*8;
    #pragma unroll
    for (int np = 0; np < 4; np++) {
        float2 f[8];
        #pragma unroll
        for (int o = 0; o < 8; o++) f[o] = upk2(acc[o][np]);
        float* p0 = gq + (u64)(sb + 2*np)*2048;
        ((float4*)p0)[0] = make_float4(f[0].x, f[1].x, f[2].x, f[3].x);
        ((float4*)p0)[1] = make_float4(f[4].x, f[5].x, f[6].x, f[7].x);
        float* p1 = gq + (u64)(sb + 2*np + 1)*2048;
        ((float4*)p1)[0] = make_float4(f[0].y, f[1].y, f[2].y, f[3].y);
        ((float4*)p1)[1] = make_float4(f[4].y, f[5].y, f[6].y, f[7].y);
    }
}

// ---------------------------------------------------------------------------
// Attention: one-pass softmax (no max-sub; |sim·scale| small), exp2 with
// folded scale, fused dot->exp->sum->V accumulate. Block=(b,head,8 s).
// ---------------------------------------------------------------------------
__global__ void __launch_bounds__(256) k_attn()
{
    __shared__ __align__(16) float ks[8][256];
    __shared__ __align__(16) float vsm[8][256];
    __shared__ __align__(16) float sctx[8*32*9];
    int warp = threadIdx.x >> 5, lane = threadIdx.x & 31;
    int blk = blockIdx.x;
    int s8   = blk & 511;
    int head = (blk >> 9) & 7;
    int b    = blk >> 12;
    int s = s8*8 + warp;
    int u = ((b << 12) + s)*8 + head;

    const float4* kp = (const float4*)(g_k + (u64)u*256);
    const float4* vp = (const float4*)(g_v + (u64)u*256);
    float4* ksw = (float4*)ks[warp];
    float4* vsw = (float4*)vsm[warp];
    ksw[lane*2]     = kp[lane*2];
    ksw[lane*2 + 1] = kp[lane*2 + 1];
    vsw[lane*2]     = vp[lane*2];
    vsw[lane*2 + 1] = vp[lane*2 + 1];

    const float4* qp = (const float4*)(g_q + (u64)u*256 + lane*8);
    float4 q0 = qp[0], q1 = qp[1];
    u64 qv0 = pk2(q0.x, q0.y), qv1 = pk2(q0.z, q0.w);
    u64 qv2 = pk2(q1.x, q1.y), qv3 = pk2(q1.z, q1.w);
    __syncwarp();

    const float CEXP = 0.35355339059327373f * 1.4426950408889634f;
    float ssA = 0.f, ssB = 0.f;
    u64 c0 = 0ull, c1 = 0ull, c2 = 0ull, c3 = 0ull;
    #pragma unroll
    for (int j = 0; j < 32; j++) {
        const ulonglong2* kq = (const ulonglong2*)&ks[warp][j*8];
        ulonglong2 ka = kq[0], kb = kq[1];
        u64 a0 = 0ull, a1 = 0ull;
        FMA2(a0, ka.x, qv0); FMA2(a1, ka.y, qv1);
        FMA2(a0, kb.x, qv2); FMA2(a1, kb.y, qv3);
        float2 f0 = upk2(a0), f1 = upk2(a1);
        float p = exp2f(((f0.x + f0.y) + (f1.x + f1.y)) * CEXP);
        if (j & 1) ssB += p; else ssA += p;
        u64 pp = pk2(p, p);
        const ulonglong2* vq = (const ulonglong2*)&vsm[warp][j*8];
        ulonglong2 va = vq[0], vb = vq[1];
        FMA2(c0, va.x, pp); FMA2(c1, va.y, pp);
        FMA2(c2, vb.x, pp); FMA2(c3, vb.y, pp);
    }

    float inv = 1.f / (ssA + ssB);
    float2 r0 = upk2(c0), r1 = upk2(c1), r2 = upk2(c2), r3 = upk2(c3);
    float vals[8] = {r0.x*inv, r0.y*inv, r1.x*inv, r1.y*inv,
                     r2.x*inv, r2.y*inv, r3.x*inv, r3.y*inv};
    #pragma unroll
    for (int e = 0; e < 8; e++)
        sctx[e*288 + lane*9 + warp] = vals[e];
    __syncthreads();

    int e = threadIdx.x >> 5, d = threadIdx.x & 31;
    const float* sp = &sctx[e*288 + d*9];
    float4 f0 = make_float4(sp[0], sp[1], sp[2], sp[3]);
    float4 f1 = make_float4(sp[4], sp[5], sp[6], sp[7]);
    float* dst = g_c + (u64)b*8388608 + (head*8 + e)*131072 + d*4096 + s8*8;
    ((float4*)dst)[0] = f0;
    ((float4*)dst)[1] = f1;
}

// ---------------------------------------------------------------------------
// O projection: same GEMM core, reads g_c (x-layout) device-side,
// contiguous stores to out.
// ---------------------------------------------------------------------------
__global__ void __launch_bounds__(256, 2) k_proj_o(const float* __restrict__ W,
                                                   float* __restrict__ out)
{
    __shared__ __align__(16) float xs[32*256];
    __shared__ __align__(16) float WA[2048];
    __shared__ __align__(16) float WB[2048];
    int b = blockIdx.x >> 9;
    int n0 = (blockIdx.x & 511) << 8;
    stage_W2(WA, WB, W);

    int ot = threadIdx.x & 7, nt = threadIdx.x >> 3;
    u64 acc[8][4];
    #pragma unroll
    for (int o = 0; o < 8; o++)
        #pragma unroll
        for (int np = 0; np < 4; np++) acc[o][np] = 0ull;

    #pragma unroll 1
    for (int kc = 0; kc < 2; kc++) {
        __syncthreads();
        stage_chunk(xs, g_c, b, n0, kc);
        __syncthreads();
        #pragma unroll 4
        for (int k = 0; k < 32; k++) {
            int kg = kc*32 + k;
            float4 wa = *(const float4*)&WA[kg*32 + ot*4];
            float4 wb = *(const float4*)&WB[kg*32 + ot*4];
            u64 ws[8] = {pk2(wa.x,wa.x), pk2(wa.y,wa.y), pk2(wa.z,wa.z), pk2(wa.w,wa.w),
                         pk2(wb.x,wb.x), pk2(wb.y,wb.y), pk2(wb.z,wb.z), pk2(wb.w,wb.w)};
            const ulonglong2* xp = (const ulonglong2*)&xs[k*256 + nt*8];
            ulonglong2 x0 = xp[0], x1 = xp[1];
            u64 xv[4] = {x0.x, x0.y, x1.x, x1.y};
            #pragma unroll
            for (int o = 0; o < 8; o++)
                #pragma unroll
                for (int np = 0; np < 4; np++)
                    FMA2(acc[o][np], ws[o], xv[np]);
        }
    }

    float* ob = out + (u64)b*8388608 + n0 + nt*8;
    #pragma unroll
    for (int o = 0; o < 8; o++) {
        float* oc = ob + (u64)(ot*8 + o)*131072;
        float2 a0 = upk2(acc[o][0]), a1 = upk2(acc[o][1]);
        float2 a2 = upk2(acc[o][2]), a3 = upk2(acc[o][3]);
        ((float4*)oc)[0] = make_float4(a0.x, a0.y, a1.x, a1.y);
        ((float4*)oc)[1] = make_float4(a2.x, a2.y, a3.x, a3.y);
    }
}

extern "C" void kernel_launch(void* const* d_in, const int* in_sizes, int n_in,
                              void* d_out, int out_size)
{
    const float* qf = (const float*)d_in[0];
    const float* kf = (const float*)d_in[1];
    const float* Wq = (const float*)d_in[2];
    const float* Wk = (const float*)d_in[3];
    const float* Wv = (const float*)d_in[4];
    const float* Wo = (const float*)d_in[5];
    float* out = (float*)d_out;

    k_proj  <<<1024, 256>>>(qf, Wq, 0);
    k_proj  <<<1024, 256>>>(kf, Wk, 1);
    k_proj  <<<1024, 256>>>(kf, Wv, 2);
    k_attn  <<<8192, 256>>>();
    k_proj_o<<<1024, 256>>>(Wo, out);
}

// round 13
// speedup vs baseline: 1.0024x; 1.0009x over previous
#include <cuda_runtime.h>

#define NEL 16777216   // B*C*D*H*W
typedef unsigned long long u64;

// Scratch. q/k/v in attention layout [b][s][head][d][e], ctx in x-layout [B][C][N].
__device__ __align__(16) float g_q[NEL];
__device__ __align__(16) float g_k[NEL];
__device__ __align__(16) float g_v[NEL];
__device__ __align__(16) float g_c[NEL];

__device__ __forceinline__ u64 pk2(float lo, float hi) {
    u64 r; asm("mov.b64 %0, {%1,%2};" : "=l"(r) : "f"(lo), "f"(hi)); return r;
}
__device__ __forceinline__ float2 upk2(u64 v) {
    float2 r; asm("mov.b64 {%0,%1}, %2;" : "=f"(r.x), "=f"(r.y) : "l"(v)); return r;
}
#define FMA2(d, a, b) asm("fma.rn.f32x2 %0, %1, %2, %0;" : "+l"(d) : "l"(a), "l"(b))

// ---------------------------------------------------------------------------
// W[64][64] ([o][k]) -> two conflict-free planes, 16B stride over ot.
// ---------------------------------------------------------------------------
__device__ __forceinline__ void stage_W2(float* A, float* B,
                                         const float* __restrict__ Wsrc) {
    for (int idx = threadIdx.x; idx < 2048; idx += 256) {
        int k = idx >> 5, t = idx & 31;
        int ot = t >> 2, j = t & 3;
        A[idx] = Wsrc[(ot*8 + j)*64 + k];
        B[idx] = Wsrc[(ot*8 + 4 + j)*64 + k];
    }
}

// Stage one 32-channel chunk of x[64][N] into xs[32][256].
__device__ __forceinline__ void stage_chunk(float* xs, const float* __restrict__ xsrc,
                                            int b, int n0, int kc) {
    const float4* xg = (const float4*)(xsrc + (u64)b*8388608 + n0);
    float4* xs4 = (float4*)xs;
    #pragma unroll
    for (int i = 0; i < 8; i++) {
        int idx = threadIdx.x + i*256;
        int c = idx >> 6, n4 = idx & 63;
        xs4[c*64 + n4] = xg[(u64)(kc*32 + c)*32768 + n4];
    }
}

// ---------------------------------------------------------------------------
// Generic projection -> attention layout [b][s][head][d][e].
// Block [64o x 256n], 256 threads, thread tile [8o x 8n], k-split 2x32.
// dst selected DEVICE-SIDE via `which` (device globals must not be passed
// from host code).
// ---------------------------------------------------------------------------
__global__ void __launch_bounds__(256, 2) k_proj(const float* __restrict__ x,
                                                 const float* __restrict__ W,
                                                 int which)
{
    __shared__ __align__(16) float xs[32*256];
    __shared__ __align__(16) float WA[2048];
    __shared__ __align__(16) float WB[2048];
    float* dst = (which == 0) ? g_q : (which == 1) ? g_k : g_v;
    int b = blockIdx.x >> 9;
    int n0 = (blockIdx.x & 511) << 8;
    stage_W2(WA, WB, W);

    int ot = threadIdx.x & 7, nt = threadIdx.x >> 3;   // n = nt*8
    u64 acc[8][4];
    #pragma unroll
    for (int o = 0; o < 8; o++)
        #pragma unroll
        for (int np = 0; np < 4; np++) acc[o][np] = 0ull;

    #pragma unroll 1
    for (int kc = 0; kc < 2; kc++) {
        __syncthreads();
        stage_chunk(xs, x, b, n0, kc);
        __syncthreads();
        #pragma unroll 4
        for (int k = 0; k < 32; k++) {
            int kg = kc*32 + k;
            float4 wa = *(const float4*)&WA[kg*32 + ot*4];
            float4 wb = *(const float4*)&WB[kg*32 + ot*4];
            u64 ws[8] = {pk2(wa.x,wa.x), pk2(wa.y,wa.y), pk2(wa.z,wa.z), pk2(wa.w,wa.w),
                         pk2(wb.x,wb.x), pk2(wb.y,wb.y), pk2(wb.z,wb.z), pk2(wb.w,wb.w)};
            const ulonglong2* xp = (const ulonglong2*)&xs[k*256 + nt*8];
            ulonglong2 x0 = xp[0], x1 = xp[1];
            u64 xv[4] = {x0.x, x0.y, x1.x, x1.y};
            #pragma unroll
            for (int o = 0; o < 8; o++)
                #pragma unroll
                for (int np = 0; np < 4; np++)
                    FMA2(acc[o][np], ws[o], xv[np]);
        }
    }

    int d = n0 >> 12;
    int sb = (n0 & 4095) + nt*8;
    float* gq = dst + (u64)b*8388608 + ot*256 + d*8;
    #pragma unroll
    for (int np = 0; np < 4; np++) {
        float2 f[8];
        #pragma unroll
        for (int o = 0; o < 8; o++) f[o] = upk2(acc[o][np]);
        float* p0 = gq + (u64)(sb + 2*np)*2048;
        ((float4*)p0)[0] = make_float4(f[0].x, f[1].x, f[2].x, f[3].x);
        ((float4*)p0)[1] = make_float4(f[4].x, f[5].x, f[6].x, f[7].x);
        float* p1 = gq + (u64)(sb + 2*np + 1)*2048;
        ((float4*)p1)[0] = make_float4(f[0].y, f[1].y, f[2].y, f[3].y);
        ((float4*)p1)[1] = make_float4(f[4].y, f[5].y, f[6].y, f[7].y);
    }
}

// ---------------------------------------------------------------------------
// Attention: one-pass softmax (no max-sub; |sim·scale| small), exp2 with
// folded scale, fused dot->exp->sum->V accumulate. Block=(b,head,8 s).
// ---------------------------------------------------------------------------
__global__ void __launch_bounds__(256) k_attn()
{
    __shared__ __align__(16) float ks[8][256];
    __shared__ __align__(16) float vsm[8][256];
    __shared__ __align__(16) float sctx[8*32*9];
    int warp = threadIdx.x >> 5, lane = threadIdx.x & 31;
    int blk = blockIdx.x;
    int s8   = blk & 511;
    int head = (blk >> 9) & 7;
    int b    = blk >> 12;
    int s = s8*8 + warp;
    int u = ((b << 12) + s)*8 + head;

    const float4* kp = (const float4*)(g_k + (u64)u*256);
    const float4* vp = (const float4*)(g_v + (u64)u*256);
    float4* ksw = (float4*)ks[warp];
    float4* vsw = (float4*)vsm[warp];
    ksw[lane*2]     = kp[lane*2];
    ksw[lane*2 + 1] = kp[lane*2 + 1];
    vsw[lane*2]     = vp[lane*2];
    vsw[lane*2 + 1] = vp[lane*2 + 1];

    const float4* qp = (const float4*)(g_q + (u64)u*256 + lane*8);
    float4 q0 = qp[0], q1 = qp[1];
    u64 qv0 = pk2(q0.x, q0.y), qv1 = pk2(q0.z, q0.w);
    u64 qv2 = pk2(q1.x, q1.y), qv3 = pk2(q1.z, q1.w);
    __syncwarp();

    const float CEXP = 0.35355339059327373f * 1.4426950408889634f;
    float ssA = 0.f, ssB = 0.f;
    u64 c0 = 0ull, c1 = 0ull, c2 = 0ull, c3 = 0ull;
    #pragma unroll
    for (int j = 0; j < 32; j++) {
        const ulonglong2* kq = (const ulonglong2*)&ks[warp][j*8];
        ulonglong2 ka = kq[0], kb = kq[1];
        u64 a0 = 0ull, a1 = 0ull;
        FMA2(a0, ka.x, qv0); FMA2(a1, ka.y, qv1);
        FMA2(a0, kb.x, qv2); FMA2(a1, kb.y, qv3);
        float2 f0 = upk2(a0), f1 = upk2(a1);
        float p = exp2f(((f0.x + f0.y) + (f1.x + f1.y)) * CEXP);
        if (j & 1) ssB += p; else ssA += p;
        u64 pp = pk2(p, p);
        const ulonglong2* vq = (const ulonglong2*)&vsm[warp][j*8];
        ulonglong2 va = vq[0], vb = vq[1];
        FMA2(c0, va.x, pp); FMA2(c1, va.y, pp);
        FMA2(c2, vb.x, pp); FMA2(c3, vb.y, pp);
    }

    float inv = 1.f / (ssA + ssB);
    float2 r0 = upk2(c0), r1 = upk2(c1), r2 = upk2(c2), r3 = upk2(c3);
    float vals[8] = {r0.x*inv, r0.y*inv, r1.x*inv, r1.y*inv,
                     r2.x*inv, r2.y*inv, r3.x*inv, r3.y*inv};
    #pragma unroll
    for (int e = 0; e < 8; e++)
        sctx[e*288 + lane*9 + warp] = vals[e];
    __syncthreads();

    int e = threadIdx.x >> 5, d = threadIdx.x & 31;
    const float* sp = &sctx[e*288 + d*9];
    float4 f0 = make_float4(sp[0], sp[1], sp[2], sp[3]);
    float4 f1 = make_float4(sp[4], sp[5], sp[6], sp[7]);
    float* dst = g_c + (u64)b*8388608 + (head*8 + e)*131072 + d*4096 + s8*8;
    ((float4*)dst)[0] = f0;
    ((float4*)dst)[1] = f1;
}

// ---------------------------------------------------------------------------
// O projection: same GEMM core, reads g_c (x-layout) device-side,
// contiguous stores to out.
// ---------------------------------------------------------------------------
__global__ void __launch_bounds__(256, 2) k_proj_o(const float* __restrict__ W,
                                                   float* __restrict__ out)
{
    __shared__ __align__(16) float xs[32*256];
    __shared__ __align__(16) float WA[2048];
    __shared__ __align__(16) float WB[2048];
    int b = blockIdx.x >> 9;
    int n0 = (blockIdx.x & 511) << 8;
    stage_W2(WA, WB, W);

    int ot = threadIdx.x & 7, nt = threadIdx.x >> 3;
    u64 acc[8][4];
    #pragma unroll
    for (int o = 0; o < 8; o++)
        #pragma unroll
        for (int np = 0; np < 4; np++) acc[o][np] = 0ull;

    #pragma unroll 1
    for (int kc = 0; kc < 2; kc++) {
        __syncthreads();
        stage_chunk(xs, g_c, b, n0, kc);
        __syncthreads();
        #pragma unroll 4
        for (int k = 0; k < 32; k++) {
            int kg = kc*32 + k;
            float4 wa = *(const float4*)&WA[kg*32 + ot*4];
            float4 wb = *(const float4*)&WB[kg*32 + ot*4];
            u64 ws[8] = {pk2(wa.x,wa.x), pk2(wa.y,wa.y), pk2(wa.z,wa.z), pk2(wa.w,wa.w),
                         pk2(wb.x,wb.x), pk2(wb.y,wb.y), pk2(wb.z,wb.z), pk2(wb.w,wb.w)};
            const ulonglong2* xp = (const ulonglong2*)&xs[k*256 + nt*8];
            ulonglong2 x0 = xp[0], x1 = xp[1];
            u64 xv[4] = {x0.x, x0.y, x1.x, x1.y};
            #pragma unroll
            for (int o = 0; o < 8; o++)
                #pragma unroll
                for (int np = 0; np < 4; np++)
                    FMA2(acc[o][np], ws[o], xv[np]);
        }
    }

    float* ob = out + (u64)b*8388608 + n0 + nt*8;
    #pragma unroll
    for (int o = 0; o < 8; o++) {
        float* oc = ob + (u64)(ot*8 + o)*131072;
        float2 a0 = upk2(acc[o][0]), a1 = upk2(acc[o][1]);
        float2 a2 = upk2(acc[o][2]), a3 = upk2(acc[o][3]);
        ((float4*)oc)[0] = make_float4(a0.x, a0.y, a1.x, a1.y);
        ((float4*)oc)[1] = make_float4(a2.x, a2.y, a3.x, a3.y);
    }
}

extern "C" void kernel_launch(void* const* d_in, const int* in_sizes, int n_in,
                              void* d_out, int out_size)
{
    const float* qf = (const float*)d_in[0];
    const float* kf = (const float*)d_in[1];
    const float* Wq = (const float*)d_in[2];
    const float* Wk = (const float*)d_in[3];
    const float* Wv = (const float*)d_in[4];
    const float* Wo = (const float*)d_in[5];
    float* out = (float*)d_out;

    k_proj  <<<1024, 256>>>(qf, Wq, 0);
    k_proj  <<<1024, 256>>>(kf, Wk, 1);
    k_proj  <<<1024, 256>>>(kf, Wv, 2);
    k_attn  <<<8192, 256>>>();
    k_proj_o<<<1024, 256>>>(Wo, out);
}

// round 14
// speedup vs baseline: 1.0068x; 1.0044x over previous
#include <cuda_runtime.h>

#define NEL 16777216   // B*C*D*H*W
typedef unsigned long long u64;

// Scratch: q/k/v in attention layout [b][s][head][d][e].
__device__ __align__(16) float g_q[NEL];
__device__ __align__(16) float g_k[NEL];
__device__ __align__(16) float g_v[NEL];

__device__ __forceinline__ u64 pk2(float lo, float hi) {
    u64 r; asm("mov.b64 %0, {%1,%2};" : "=l"(r) : "f"(lo), "f"(hi)); return r;
}
__device__ __forceinline__ float2 upk2(u64 v) {
    float2 r; asm("mov.b64 {%0,%1}, %2;" : "=f"(r.x), "=f"(r.y) : "l"(v)); return r;
}
#define FMA2(d, a, b) asm("fma.rn.f32x2 %0, %1, %2, %0;" : "+l"(d) : "l"(a), "l"(b))

// ---------------------------------------------------------------------------
// W[64][64] ([o][k]) -> two conflict-free planes, 16B stride over ot. (proven)
// ---------------------------------------------------------------------------
__device__ __forceinline__ void stage_W2(float* A, float* B,
                                         const float* __restrict__ Wsrc) {
    for (int idx = threadIdx.x; idx < 2048; idx += 256) {
        int k = idx >> 5, t = idx & 31;
        int ot = t >> 2, j = t & 3;
        A[idx] = Wsrc[(ot*8 + j)*64 + k];
        B[idx] = Wsrc[(ot*8 + 4 + j)*64 + k];
    }
}

__device__ __forceinline__ void stage_chunk(float* xs, const float* __restrict__ xsrc,
                                            int b, int n0, int kc) {
    const float4* xg = (const float4*)(xsrc + (u64)b*8388608 + n0);
    float4* xs4 = (float4*)xs;
    #pragma unroll
    for (int i = 0; i < 8; i++) {
        int idx = threadIdx.x + i*256;
        int c = idx >> 6, n4 = idx & 63;
        xs4[c*64 + n4] = xg[(u64)(kc*32 + c)*32768 + n4];
    }
}

// ---------------------------------------------------------------------------
// Q/K/V projection (proven, unchanged). dst selected device-side.
// ---------------------------------------------------------------------------
__global__ void __launch_bounds__(256, 2) k_proj(const float* __restrict__ x,
                                                 const float* __restrict__ W,
                                                 int which)
{
    __shared__ __align__(16) float xs[32*256];
    __shared__ __align__(16) float WA[2048];
    __shared__ __align__(16) float WB[2048];
    float* dst = (which == 0) ? g_q : (which == 1) ? g_k : g_v;
    int b = blockIdx.x >> 9;
    int n0 = (blockIdx.x & 511) << 8;
    stage_W2(WA, WB, W);

    int ot = threadIdx.x & 7, nt = threadIdx.x >> 3;
    u64 acc[8][4];
    #pragma unroll
    for (int o = 0; o < 8; o++)
        #pragma unroll
        for (int np = 0; np < 4; np++) acc[o][np] = 0ull;

    #pragma unroll 1
    for (int kc = 0; kc < 2; kc++) {
        __syncthreads();
        stage_chunk(xs, x, b, n0, kc);
        __syncthreads();
        #pragma unroll 4
        for (int k = 0; k < 32; k++) {
            int kg = kc*32 + k;
            float4 wa = *(const float4*)&WA[kg*32 + ot*4];
            float4 wb = *(const float4*)&WB[kg*32 + ot*4];
            u64 ws[8] = {pk2(wa.x,wa.x), pk2(wa.y,wa.y), pk2(wa.z,wa.z), pk2(wa.w,wa.w),
                         pk2(wb.x,wb.x), pk2(wb.y,wb.y), pk2(wb.z,wb.z), pk2(wb.w,wb.w)};
            const ulonglong2* xp = (const ulonglong2*)&xs[k*256 + nt*8];
            ulonglong2 x0 = xp[0], x1 = xp[1];
            u64 xv[4] = {x0.x, x0.y, x1.x, x1.y};
            #pragma unroll
            for (int o = 0; o < 8; o++)
                #pragma unroll
                for (int np = 0; np < 4; np++)
                    FMA2(acc[o][np], ws[o], xv[np]);
        }
    }

    int d = n0 >> 12;
    int sb = (n0 & 4095) + nt*8;
    float* gq = dst + (u64)b*8388608 + ot*256 + d*8;
    #pragma unroll
    for (int np = 0; np < 4; np++) {
        float2 f[8];
        #pragma unroll
        for (int o = 0; o < 8; o++) f[o] = upk2(acc[o][np]);
        float* p0 = gq + (u64)(sb + 2*np)*2048;
        ((float4*)p0)[0] = make_float4(f[0].x, f[1].x, f[2].x, f[3].x);
        ((float4*)p0)[1] = make_float4(f[4].x, f[5].x, f[6].x, f[7].x);
        float* p1 = gq + (u64)(sb + 2*np + 1)*2048;
        ((float4*)p1)[0] = make_float4(f[0].y, f[1].y, f[2].y, f[3].y);
        ((float4*)p1)[1] = make_float4(f[4].y, f[5].y, f[6].y, f[7].y);
    }
}

// ---------------------------------------------------------------------------
// Fused attention + O projection.
// Block = (b, 8 consecutive s, ALL 8 heads). 512 threads = 16 warps.
// Warp w: sw = w&7 (s within group), hh = w>>3; handles heads hh*4..hh*4+3
// with the proven per-unit inner loop. ctx accumulated in smem
// sctx[c][d*12 + sw] (64 x 384 floats), then a balanced GEMM epilogue
// ([4o x 8loc] per thread) applies Wo and stores straight to out.
// Dynamic smem: ks 16*256 | vs 16*256 | sctx 64*384 | WT 64*64 = 36864 floats.
// ---------------------------------------------------------------------------
__global__ void __launch_bounds__(512) k_attn_o(const float* __restrict__ Wo,
                                                float* __restrict__ out)
{
    extern __shared__ __align__(16) float sm[];
    float* ksw  = sm + threadIdx.x / 32 * 256;          // per-warp K tile
    float* vsw  = sm + 4096 + threadIdx.x / 32 * 256;   // per-warp V tile
    float* sctx = sm + 8192;                             // [c][d*12 + sw]
    float* WT   = sm + 8192 + 24576;                     // WT[k*64 + o]

    int tid = threadIdx.x;
    int warp = tid >> 5, lane = tid & 31;
    int sw = warp & 7, hh = warp >> 3;
    int blk = blockIdx.x;
    int s8 = blk & 511, b = blk >> 9;
    int s = s8*8 + sw;

    // stage transposed Wo (used only after the pre-epilogue barrier)
    for (int idx = tid; idx < 4096; idx += 512)
        WT[idx] = Wo[(idx & 63)*64 + (idx >> 6)];

    const float CEXP = 0.35355339059327373f * 1.4426950408889634f;

    #pragma unroll 1
    for (int hi = 0; hi < 4; hi++) {
        int head = hh*4 + hi;
        u64 u = (u64)(((b << 12) + s)*8 + head);

        __syncwarp();   // previous iteration's reads of ksw/vsw complete
        {
            const float4* kp = (const float4*)(g_k + u*256);
            const float4* vp = (const float4*)(g_v + u*256);
            ((float4*)ksw)[lane*2]     = kp[lane*2];
            ((float4*)ksw)[lane*2 + 1] = kp[lane*2 + 1];
            ((float4*)vsw)[lane*2]     = vp[lane*2];
            ((float4*)vsw)[lane*2 + 1] = vp[lane*2 + 1];
        }
        const float4* qp = (const float4*)(g_q + u*256 + lane*8);
        float4 q0 = qp[0], q1 = qp[1];
        u64 qv0 = pk2(q0.x, q0.y), qv1 = pk2(q0.z, q0.w);
        u64 qv2 = pk2(q1.x, q1.y), qv3 = pk2(q1.z, q1.w);
        __syncwarp();

        float ssA = 0.f, ssB = 0.f;
        u64 c0 = 0ull, c1 = 0ull, c2 = 0ull, c3 = 0ull;
        #pragma unroll
        for (int j = 0; j < 32; j++) {
            const ulonglong2* kq = (const ulonglong2*)&ksw[j*8];
            ulonglong2 ka = kq[0], kb = kq[1];
            u64 a0 = 0ull, a1 = 0ull;
            FMA2(a0, ka.x, qv0); FMA2(a1, ka.y, qv1);
            FMA2(a0, kb.x, qv2); FMA2(a1, kb.y, qv3);
            float2 f0 = upk2(a0), f1 = upk2(a1);
            float p = exp2f(((f0.x + f0.y) + (f1.x + f1.y)) * CEXP);
            if (j & 1) ssB += p; else ssA += p;
            u64 pp = pk2(p, p);
            const ulonglong2* vq = (const ulonglong2*)&vsw[j*8];
            ulonglong2 va = vq[0], vb = vq[1];
            FMA2(c0, va.x, pp); FMA2(c1, va.y, pp);
            FMA2(c2, vb.x, pp); FMA2(c3, vb.y, pp);
        }

        float inv = 1.f / (ssA + ssB);
        float2 r0 = upk2(c0), r1 = upk2(c1), r2 = upk2(c2), r3 = upk2(c3);
        float vals[8] = {r0.x*inv, r0.y*inv, r1.x*inv, r1.y*inv,
                         r2.x*inv, r2.y*inv, r3.x*inv, r3.y*inv};
        #pragma unroll
        for (int e = 0; e < 8; e++)
            sctx[(head*8 + e)*384 + lane*12 + sw] = vals[e];   // lane = d
    }
    __syncthreads();

    // ---- epilogue GEMM: out[64 c][256 loc] = Wo x ctx, K=64 ----
    // thread tile [4o x 8loc]; ot = tid&15, nt = tid>>4 = d (0..31).
    {
        int ot = tid & 15, nt = tid >> 4;
        u64 acc[4][4];
        #pragma unroll
        for (int o = 0; o < 4; o++)
            #pragma unroll
            for (int np = 0; np < 4; np++) acc[o][np] = 0ull;

        #pragma unroll 4
        for (int k = 0; k < 64; k++) {
            float4 wt = *(const float4*)&WT[k*64 + ot*4];
            u64 ws[4] = {pk2(wt.x,wt.x), pk2(wt.y,wt.y), pk2(wt.z,wt.z), pk2(wt.w,wt.w)};
            const float4* xp = (const float4*)&sctx[k*384 + nt*12];
            float4 xa = xp[0], xb = xp[1];
            u64 xv[4] = {pk2(xa.x,xa.y), pk2(xa.z,xa.w), pk2(xb.x,xb.y), pk2(xb.z,xb.w)};
            #pragma unroll
            for (int o = 0; o < 4; o++)
                #pragma unroll
                for (int np = 0; np < 4; np++)
                    FMA2(acc[o][np], ws[o], xv[np]);
        }

        float* ob = out + (u64)b*8388608 + nt*4096 + s8*8;
        #pragma unroll
        for (int o = 0; o < 4; o++) {
            float* oc = ob + (u64)(ot*4 + o)*131072;
            float2 a0 = upk2(acc[o][0]), a1 = upk2(acc[o][1]);
            float2 a2 = upk2(acc[o][2]), a3 = upk2(acc[o][3]);
            ((float4*)oc)[0] = make_float4(a0.x, a0.y, a1.x, a1.y);
            ((float4*)oc)[1] = make_float4(a2.x, a2.y, a3.x, a3.y);
        }
    }
}

extern "C" void kernel_launch(void* const* d_in, const int* in_sizes, int n_in,
                              void* d_out, int out_size)
{
    const float* qf = (const float*)d_in[0];
    const float* kf = (const float*)d_in[1];
    const float* Wq = (const float*)d_in[2];
    const float* Wk = (const float*)d_in[3];
    const float* Wv = (const float*)d_in[4];
    const float* Wo = (const float*)d_in[5];
    float* out = (float*)d_out;

    const int ATTN_SMEM = 36864 * 4;   // 144 KB dynamic shared
    cudaFuncSetAttribute(k_attn_o, cudaFuncAttributeMaxDynamicSharedMemorySize,
                         ATTN_SMEM);

    k_proj  <<<1024, 256>>>(qf, Wq, 0);
    k_proj  <<<1024, 256>>>(kf, Wk, 1);
    k_proj  <<<1024, 256>>>(kf, Wv, 2);
    k_attn_o<<<1024, 512, ATTN_SMEM>>>(Wo, out);
}